// round 13
// baseline (speedup 1.0000x reference)
#include <cuda_runtime.h>
#include <cuda_fp16.h>
#include <cstdint>

// ---------------------------------------------------------------------------
// QWenAttention: B=1, S=2048, H=2048, NH=16, HD=128
//   qkv = hidden @ w_qkv + b_qkv; rope(q,k); ctx = causal_attn(q,k,v);
//   out = ctx @ w_proj
// fp16 mma.sync m16n8k16 (fp32 accum); ldmatrix fragments; GEMM 128x128
// 2-stage cp.async (validated R10 geometry) with RoPE fused into the QKV
// epilogue via warp-pair smem exchange (fp32, pre-rounding). Flash = R10.
// ---------------------------------------------------------------------------

#define S_LEN 2048
#define HID   2048
#define NHEAD 16
#define HDIM  128
#define QKV_N 6144

__device__ __align__(16) __half g_qkv_h[S_LEN * QKV_N];
__device__ __align__(16) __half g_ctx_h[S_LEN * HID];
__device__ __align__(16) __half g_hid_h[S_LEN * HID];
__device__ __align__(16) __half g_w1t_h[QKV_N * HID];   // [N,K]
__device__ __align__(16) __half g_w2t_h[HID * HID];     // [N,K]
__device__ __align__(16) float  g_cos[S_LEN * 64];
__device__ __align__(16) float  g_sin[S_LEN * 64];

// ---------------------------------------------------------------------------
// helpers
// ---------------------------------------------------------------------------
__device__ __forceinline__ void mma_fp16(float* c, const uint32_t* a, const uint32_t* b) {
    asm volatile(
        "mma.sync.aligned.m16n8k16.row.col.f32.f16.f16.f32 "
        "{%0,%1,%2,%3}, {%4,%5,%6,%7}, {%8,%9}, {%0,%1,%2,%3};\n"
        : "+f"(c[0]), "+f"(c[1]), "+f"(c[2]), "+f"(c[3])
        : "r"(a[0]), "r"(a[1]), "r"(a[2]), "r"(a[3]), "r"(b[0]), "r"(b[1]));
}
__device__ __forceinline__ void ldsm_x4(uint32_t* r, uint32_t addr) {
    asm volatile("ldmatrix.sync.aligned.m8n8.x4.shared.b16 {%0,%1,%2,%3}, [%4];"
        : "=r"(r[0]), "=r"(r[1]), "=r"(r[2]), "=r"(r[3]) : "r"(addr));
}
__device__ __forceinline__ void ldsm_x4_t(uint32_t* r, uint32_t addr) {
    asm volatile("ldmatrix.sync.aligned.m8n8.x4.trans.shared.b16 {%0,%1,%2,%3}, [%4];"
        : "=r"(r[0]), "=r"(r[1]), "=r"(r[2]), "=r"(r[3]) : "r"(addr));
}
__device__ __forceinline__ void cpa16u(uint32_t s, const void* g) {
    asm volatile("cp.async.cg.shared.global [%0], [%1], 16;\n" :: "r"(s), "l"(g));
}
__device__ __forceinline__ uint32_t smem_u32(const void* p) {
    return (uint32_t)__cvta_generic_to_shared(p);
}
__device__ __forceinline__ uint32_t pack_h2(float lo, float hi) {
    __half2 h = __floats2half2_rn(lo, hi);
    return *(uint32_t*)&h;
}

// ---------------------------------------------------------------------------
// prep kernels
// ---------------------------------------------------------------------------
__global__ void convert_half_kernel(const float* __restrict__ in,
                                    __half* __restrict__ out, int n4)
{
    int i = blockIdx.x * blockDim.x + threadIdx.x;
    if (i >= n4) return;
    float4 v = ((const float4*)in)[i];
    ((__half2*)out)[i * 2]     = __floats2half2_rn(v.x, v.y);
    ((__half2*)out)[i * 2 + 1] = __floats2half2_rn(v.z, v.w);
}

__global__ void transpose_half_kernel(const float* __restrict__ in,
                                      __half* __restrict__ out, int R, int C)
{
    __shared__ float tile[32][33];
    int c0 = blockIdx.x * 32, r0 = blockIdx.y * 32;
    int tx = threadIdx.x, ty = threadIdx.y;
#pragma unroll
    for (int i = 0; i < 32; i += 8)
        tile[ty + i][tx] = in[(size_t)(r0 + ty + i) * C + c0 + tx];
    __syncthreads();
#pragma unroll
    for (int i = 0; i < 32; i += 8)
        out[(size_t)(c0 + ty + i) * R + r0 + tx] = __float2half(tile[tx][ty + i]);
}

__global__ void rope_table_kernel()
{
    int idx = blockIdx.x * blockDim.x + threadIdx.x;
    if (idx >= S_LEN * 64) return;
    int i = idx & 63;
    int s = idx >> 6;
    double invf_d = pow(10000.0, -(double)(2 * i) / 128.0);
    float invf_f  = (float)invf_d;
    float ang_f   = (float)s * invf_f;
    double ds, dc;
    sincos((double)ang_f, &ds, &dc);
    g_cos[idx] = (float)dc;
    g_sin[idx] = (float)ds;
}

// ---------------------------------------------------------------------------
// fp16 GEMM: C[M,N] = A[M,K] @ Bt^T (+bias, +optional fused rope on q/k).
// Block 128x128x32, 8 warps (4Mx2N), warp 32x64. ldmatrix fragments,
// cp.async 2-stage, static smem pool 40KB (reused for the rope exchange).
// Rope: after mainloop, warp pair (2w,2w+1) shares rows; partner element
// col^64 exchanged through smem (stride 132), applied in fp32 pre-rounding.
// ---------------------------------------------------------------------------
#define GW 20
#define ASTG (128 * GW)   // words per A stage (=2560)
#define XST 132           // rope exchange row stride (words)

template <bool HAS_BIAS, bool DO_ROPE, typename OutT>
__global__ __launch_bounds__(256) void gemm_fp16_kernel(
    const __half* __restrict__ A, const __half* __restrict__ Bt,
    const float* __restrict__ bias, OutT* __restrict__ C,
    int M, int N, int K)
{
    __shared__ __align__(16) uint32_t pool[4 * ASTG];   // As[2] | Bs[2], 40KB

    const int tid  = threadIdx.x;
    const int warp = tid >> 5;
    const int lane = tid & 31;
    const int wm = (warp >> 1) * 32;
    const int wn = (warp & 1) * 64;
    const int m0 = blockIdx.y * 128;
    const int n0 = blockIdx.x * 128;

    const int l8  = lane & 7, sel = lane >> 3;
    const int a_row = l8 + ((sel & 1) << 3), a_col = (sel >> 1) << 2;  // A-type
    const int b_row = l8 + ((sel >> 1) << 3), b_col = (sel & 1) << 2;  // B-type

    float acc[2][8][4];
#pragma unroll
    for (int i = 0; i < 2; i++)
#pragma unroll
        for (int j = 0; j < 8; j++)
#pragma unroll
            for (int c = 0; c < 4; c++) acc[i][j][c] = 0.f;

    const int row = tid >> 1;
    const int jb  = (tid & 1) * 2;

    auto load_stage = [&](int st, int kb) {
        uint32_t* As = pool + st * ASTG;
        uint32_t* Bs = pool + (2 + st) * ASTG;
#pragma unroll
        for (int j = 0; j < 2; j++) {
            int ch = jb + j;
            cpa16u(smem_u32(&As[row * GW + ch * 4]),
                   A + (size_t)(m0 + row) * K + kb + ch * 8);
            cpa16u(smem_u32(&Bs[row * GW + ch * 4]),
                   Bt + (size_t)(n0 + row) * K + kb + ch * 8);
        }
        asm volatile("cp.async.commit_group;\n" ::);
    };

    const int nk = K / 32;
    load_stage(0, 0);

    for (int t = 0; t < nk; t++) {
        if (t + 1 < nk) {
            load_stage((t + 1) & 1, (t + 1) * 32);
            asm volatile("cp.async.wait_group 1;\n" ::);
        } else {
            asm volatile("cp.async.wait_group 0;\n" ::);
        }
        __syncthreads();
        const uint32_t* Asm = pool + (t & 1) * ASTG;
        const uint32_t* Bsm = pool + (2 + (t & 1)) * ASTG;

#pragma unroll
        for (int step = 0; step < 2; step++) {
            uint32_t a[2][4];
#pragma unroll
            for (int mf = 0; mf < 2; mf++)
                ldsm_x4(a[mf], smem_u32(&Asm[(wm + mf * 16 + a_row) * GW + step * 8 + a_col]));
#pragma unroll
            for (int nfp = 0; nfp < 4; nfp++) {
                uint32_t b[4];
                ldsm_x4(b, smem_u32(&Bsm[(wn + nfp * 16 + b_row) * GW + step * 8 + b_col]));
                mma_fp16(acc[0][2 * nfp],     a[0], b);
                mma_fp16(acc[1][2 * nfp],     a[1], b);
                mma_fp16(acc[0][2 * nfp + 1], a[0], b + 2);
                mma_fp16(acc[1][2 * nfp + 1], a[1], b + 2);
            }
        }
        __syncthreads();
    }

    const int lr = lane >> 2, lc = lane & 3;

    // bias (before rope, matching reference order)
    if (HAS_BIAS) {
#pragma unroll
        for (int nf = 0; nf < 8; nf++) {
            float b0 = bias[n0 + wn + nf * 8 + 2 * lc];
            float b1 = bias[n0 + wn + nf * 8 + 2 * lc + 1];
#pragma unroll
            for (int mf = 0; mf < 2; mf++) {
                acc[mf][nf][0] += b0; acc[mf][nf][1] += b1;
                acc[mf][nf][2] += b0; acc[mf][nf][3] += b1;
            }
        }
    }

    // fused rope on q/k tiles (tile == one head; partner col^64 in pair warp)
    if (DO_ROPE && n0 < 2 * HID) {
        float* xb = (float*)pool;            // 4 pairs x 16 rows x 132 stride
        const int pair = warp >> 1;
#pragma unroll
        for (int mf = 0; mf < 2; mf++) {
#pragma unroll
            for (int nf = 0; nf < 8; nf++)
#pragma unroll
                for (int c = 0; c < 4; c++) {
                    int r   = lr + ((c >> 1) << 3);
                    int col = wn + nf * 8 + 2 * lc + (c & 1);
                    xb[(pair * 16 + r) * XST + col] = acc[mf][nf][c];
                }
            __syncthreads();
#pragma unroll
            for (int nf = 0; nf < 8; nf++)
#pragma unroll
                for (int c = 0; c < 4; c++) {
                    int r   = lr + ((c >> 1) << 3);
                    int col = wn + nf * 8 + 2 * lc + (c & 1);
                    float partner = xb[(pair * 16 + r) * XST + (col ^ 64)];
                    int srow = m0 + wm + mf * 16 + r;
                    int j    = col & 63;
                    float cs = g_cos[srow * 64 + j];
                    float sn = g_sin[srow * 64 + j];
                    float v  = acc[mf][nf][c];
                    acc[mf][nf][c] = (col < 64) ? (v * cs - partner * sn)
                                                : (v * cs + partner * sn);
                }
            if (mf == 0) __syncthreads();   // protect phase-2 overwrite
        }
    }

#pragma unroll
    for (int mf = 0; mf < 2; mf++)
#pragma unroll
        for (int nf = 0; nf < 8; nf++) {
            int r0i = m0 + wm + mf * 16 + lr;
            int col = n0 + wn + nf * 8 + 2 * lc;
            if (sizeof(OutT) == 2) {
                *(__half2*)((__half*)C + (size_t)r0i * N + col) =
                    __floats2half2_rn(acc[mf][nf][0], acc[mf][nf][1]);
                *(__half2*)((__half*)C + (size_t)(r0i + 8) * N + col) =
                    __floats2half2_rn(acc[mf][nf][2], acc[mf][nf][3]);
            } else {
                float* c0p = (float*)C + (size_t)r0i * N + col;
                float* c1p = (float*)C + (size_t)(r0i + 8) * N + col;
                c0p[0] = acc[mf][nf][0]; c0p[1] = acc[mf][nf][1];
                c1p[0] = acc[mf][nf][2]; c1p[1] = acc[mf][nf][3];
            }
        }
}

// ---------------------------------------------------------------------------
// fp16 flash attention, causal (UNCHANGED from round 10 — validated).
// ---------------------------------------------------------------------------
#define KW 68
#define PW 20

__global__ __launch_bounds__(256) void flash_fp16_kernel(
    const __half* __restrict__ qkv, __half* __restrict__ ctx)
{
    __shared__ __align__(16) uint32_t Ks[2][32 * KW];
    __shared__ __align__(16) uint32_t Vs[2][32 * KW];
    __shared__ __align__(16) uint32_t Ps[8 * 16 * PW];

    const int tid  = threadIdx.x;
    const int warp = tid >> 5;
    const int lane = tid & 31;
    const int lr = lane >> 2;
    const int lc = lane & 3;
    const int qt = 15 - blockIdx.x;
    const int h  = blockIdx.y;
    const int q0 = qt * 128;
    const float scale = 0.08838834764831845f;

    const int l8  = lane & 7, sel = lane >> 3;
    const int a_row = l8 + ((sel & 1) << 3), a_col = (sel >> 1) << 2;
    const int b_row = l8 + ((sel >> 1) << 3), b_col = (sel & 1) << 2;

    uint32_t qa[8][4];
    {
        const __half* Qb = qkv + (size_t)(q0 + warp * 16) * QKV_N + h * HDIM;
#pragma unroll
        for (int st = 0; st < 8; st++) {
            qa[st][0] = *(const uint32_t*)(Qb + (size_t)lr       * QKV_N + st * 16 + 2 * lc);
            qa[st][1] = *(const uint32_t*)(Qb + (size_t)(lr + 8) * QKV_N + st * 16 + 2 * lc);
            qa[st][2] = *(const uint32_t*)(Qb + (size_t)lr       * QKV_N + st * 16 + 2 * lc + 8);
            qa[st][3] = *(const uint32_t*)(Qb + (size_t)(lr + 8) * QKV_N + st * 16 + 2 * lc + 8);
        }
    }

    float o[16][4];
#pragma unroll
    for (int i = 0; i < 16; i++)
#pragma unroll
        for (int c = 0; c < 4; c++) o[i][c] = 0.f;
    float mA = -1e30f, mB = -1e30f, lA = 0.f, lB = 0.f;

    const int rowA = q0 + warp * 16 + lr;
    const int rowB = rowA + 8;
    const int rowMaxWarp = q0 + warp * 16 + 15;
    const int ntiles = qt * 4 + 4;

    auto load_tile = [&](int st, int jt) {
#pragma unroll
        for (int it = 0; it < 2; it++) {
            int id  = tid + it * 256;
            int key = id >> 4;
            int ch  = id & 15;
            const __half* Kg = qkv + (size_t)(jt * 32 + key) * QKV_N + HID + h * HDIM + ch * 8;
            cpa16u(smem_u32(&Ks[st][key * KW + ch * 4]), Kg);
            cpa16u(smem_u32(&Vs[st][key * KW + ch * 4]), Kg + HID);
        }
        asm volatile("cp.async.commit_group;\n" ::);
    };

    load_tile(0, 0);

    for (int j = 0; j < ntiles; j++) {
        asm volatile("cp.async.wait_group 0;\n" ::);
        __syncthreads();
        if (j + 1 < ntiles) load_tile((j + 1) & 1, j + 1);

        const uint32_t* Ksm = Ks[j & 1];
        const uint32_t* Vsm = Vs[j & 1];
        const bool active = (j * 32 <= rowMaxWarp);
        if (active) {
            float s[4][4];
#pragma unroll
            for (int nf = 0; nf < 4; nf++)
#pragma unroll
                for (int c = 0; c < 4; c++) s[nf][c] = 0.f;
#pragma unroll
            for (int st = 0; st < 8; st++) {
#pragma unroll
                for (int nfp = 0; nfp < 2; nfp++) {
                    uint32_t b[4];
                    ldsm_x4(b, smem_u32(&Ksm[(nfp * 16 + b_row) * KW + st * 8 + b_col]));
                    mma_fp16(s[2 * nfp],     qa[st], b);
                    mma_fp16(s[2 * nfp + 1], qa[st], b + 2);
                }
            }

#pragma unroll
            for (int nf = 0; nf < 4; nf++) {
                int col0 = j * 32 + nf * 8 + 2 * lc;
                s[nf][0] = (col0     > rowA) ? -1e30f : s[nf][0] * scale;
                s[nf][1] = (col0 + 1 > rowA) ? -1e30f : s[nf][1] * scale;
                s[nf][2] = (col0     > rowB) ? -1e30f : s[nf][2] * scale;
                s[nf][3] = (col0 + 1 > rowB) ? -1e30f : s[nf][3] * scale;
            }

            float tA = -1e30f, tB = -1e30f;
#pragma unroll
            for (int nf = 0; nf < 4; nf++) {
                tA = fmaxf(tA, fmaxf(s[nf][0], s[nf][1]));
                tB = fmaxf(tB, fmaxf(s[nf][2], s[nf][3]));
            }
            tA = fmaxf(tA, __shfl_xor_sync(0xffffffffu, tA, 1));
            tA = fmaxf(tA, __shfl_xor_sync(0xffffffffu, tA, 2));
            tB = fmaxf(tB, __shfl_xor_sync(0xffffffffu, tB, 1));
            tB = fmaxf(tB, __shfl_xor_sync(0xffffffffu, tB, 2));

            float mAn = fmaxf(mA, tA), mBn = fmaxf(mB, tB);
            float aA = __expf(mA - mAn), aB = __expf(mB - mBn);
            float sA = 0.f, sB = 0.f;
#pragma unroll
            for (int nf = 0; nf < 4; nf++) {
                s[nf][0] = __expf(s[nf][0] - mAn);
                s[nf][1] = __expf(s[nf][1] - mAn);
                s[nf][2] = __expf(s[nf][2] - mBn);
                s[nf][3] = __expf(s[nf][3] - mBn);
                sA += s[nf][0] + s[nf][1];
                sB += s[nf][2] + s[nf][3];
            }
            sA += __shfl_xor_sync(0xffffffffu, sA, 1);
            sA += __shfl_xor_sync(0xffffffffu, sA, 2);
            sB += __shfl_xor_sync(0xffffffffu, sB, 1);
            sB += __shfl_xor_sync(0xffffffffu, sB, 2);
            lA = lA * aA + sA;
            lB = lB * aB + sB;
            mA = mAn; mB = mBn;
#pragma unroll
            for (int nf = 0; nf < 16; nf++) {
                o[nf][0] *= aA; o[nf][1] *= aA;
                o[nf][2] *= aB; o[nf][3] *= aB;
            }

            uint32_t* P = Ps + warp * 16 * PW;
#pragma unroll
            for (int nf = 0; nf < 4; nf++) {
                P[lr       * PW + nf * 4 + lc] = pack_h2(s[nf][0], s[nf][1]);
                P[(lr + 8) * PW + nf * 4 + lc] = pack_h2(s[nf][2], s[nf][3]);
            }
            __syncwarp();

#pragma unroll
            for (int st = 0; st < 2; st++) {
                uint32_t pa[4];
                ldsm_x4(pa, smem_u32(&P[a_row * PW + st * 8 + a_col]));
#pragma unroll
                for (int nfp = 0; nfp < 8; nfp++) {
                    uint32_t b[4];
                    ldsm_x4_t(b, smem_u32(&Vsm[(st * 16 + a_row) * KW + nfp * 8 + a_col]));
                    mma_fp16(o[2 * nfp],     pa, b);
                    mma_fp16(o[2 * nfp + 1], pa, b + 2);
                }
            }
        }
    }

    float rA = 1.f / lA, rB = 1.f / lB;
#pragma unroll
    for (int nf = 0; nf < 16; nf++) {
        int col = h * HDIM + nf * 8 + 2 * lc;
        *(__half2*)(ctx + (size_t)rowA * HID + col) =
            __floats2half2_rn(o[nf][0] * rA, o[nf][1] * rA);
        *(__half2*)(ctx + (size_t)rowB * HID + col) =
            __floats2half2_rn(o[nf][2] * rB, o[nf][3] * rB);
    }
}

// ---------------------------------------------------------------------------
// launcher
// ---------------------------------------------------------------------------
extern "C" void kernel_launch(void* const* d_in, const int* in_sizes, int n_in,
                              void* d_out, int out_size)
{
    const float* hidden = nullptr;
    const float* w_qkv  = nullptr;
    const float* b_qkv  = nullptr;
    const float* w_proj = nullptr;
    for (int i = 0; i < n_in; i++) {
        long sz = in_sizes[i];
        const float* p = (const float*)d_in[i];
        if (sz == (long)HID * QKV_N)      w_qkv = p;
        else if (sz == (long)QKV_N)       b_qkv = p;
        else {
            if (!hidden) hidden = p; else w_proj = p;
        }
    }
    float* out = (float*)d_out;

    __half *qkv_h, *ctx_h, *hid_h, *w1t, *w2t;
    cudaGetSymbolAddress((void**)&qkv_h, g_qkv_h);
    cudaGetSymbolAddress((void**)&ctx_h, g_ctx_h);
    cudaGetSymbolAddress((void**)&hid_h, g_hid_h);
    cudaGetSymbolAddress((void**)&w1t,   g_w1t_h);
    cudaGetSymbolAddress((void**)&w2t,   g_w2t_h);

    rope_table_kernel<<<(S_LEN * 64) / 256, 256>>>();
    convert_half_kernel<<<(S_LEN * HID / 4) / 256, 256>>>(hidden, hid_h, S_LEN * HID / 4);
    transpose_half_kernel<<<dim3(QKV_N / 32, HID / 32), dim3(32, 8)>>>(w_qkv, w1t, HID, QKV_N);
    transpose_half_kernel<<<dim3(HID / 32, HID / 32), dim3(32, 8)>>>(w_proj, w2t, HID, HID);

    // qkv = hidden @ w_qkv + b, rope fused in epilogue
    gemm_fp16_kernel<true, true, __half><<<dim3(QKV_N / 128, S_LEN / 128), 256>>>(
        hid_h, w1t, b_qkv, qkv_h, S_LEN, QKV_N, HID);
    // attention
    flash_fp16_kernel<<<dim3(S_LEN / 128, NHEAD), 256>>>(qkv_h, ctx_h);
    // out = ctx @ w_proj
    gemm_fp16_kernel<false, false, float><<<dim3(HID / 128, S_LEN / 128), 256>>>(
        ctx_h, w2t, nullptr, out, S_LEN, HID, HID);
}

// round 14
// speedup vs baseline: 1.2387x; 1.2387x over previous
#include <cuda_runtime.h>
#include <cuda_fp16.h>
#include <cstdint>

// ---------------------------------------------------------------------------
// QWenAttention: B=1, S=2048, H=2048, NH=16, HD=128
//   qkv = hidden @ w_qkv + b_qkv; rope(q,k); ctx = causal_attn(q,k,v);
//   out = ctx @ w_proj
// fp16 mma.sync m16n8k16 (fp32 accum); ldmatrix fragments; GEMM = exact
// round-10 champion (128x128, 2-stage cp.async, separate rope kernel).
// Flash: R10 + FA2 P-fragment identity (C-layout == A-layout, no smem P).
// ---------------------------------------------------------------------------

#define S_LEN 2048
#define HID   2048
#define NHEAD 16
#define HDIM  128
#define QKV_N 6144

__device__ __align__(16) __half g_qkv_h[S_LEN * QKV_N];
__device__ __align__(16) __half g_ctx_h[S_LEN * HID];
__device__ __align__(16) __half g_hid_h[S_LEN * HID];
__device__ __align__(16) __half g_w1t_h[QKV_N * HID];   // [N,K]
__device__ __align__(16) __half g_w2t_h[HID * HID];     // [N,K]
__device__ __align__(16) float  g_cos[S_LEN * 64];
__device__ __align__(16) float  g_sin[S_LEN * 64];

// ---------------------------------------------------------------------------
// helpers
// ---------------------------------------------------------------------------
__device__ __forceinline__ void mma_fp16(float* c, const uint32_t* a, const uint32_t* b) {
    asm volatile(
        "mma.sync.aligned.m16n8k16.row.col.f32.f16.f16.f32 "
        "{%0,%1,%2,%3}, {%4,%5,%6,%7}, {%8,%9}, {%0,%1,%2,%3};\n"
        : "+f"(c[0]), "+f"(c[1]), "+f"(c[2]), "+f"(c[3])
        : "r"(a[0]), "r"(a[1]), "r"(a[2]), "r"(a[3]), "r"(b[0]), "r"(b[1]));
}
__device__ __forceinline__ void ldsm_x4(uint32_t* r, uint32_t addr) {
    asm volatile("ldmatrix.sync.aligned.m8n8.x4.shared.b16 {%0,%1,%2,%3}, [%4];"
        : "=r"(r[0]), "=r"(r[1]), "=r"(r[2]), "=r"(r[3]) : "r"(addr));
}
__device__ __forceinline__ void ldsm_x4_t(uint32_t* r, uint32_t addr) {
    asm volatile("ldmatrix.sync.aligned.m8n8.x4.trans.shared.b16 {%0,%1,%2,%3}, [%4];"
        : "=r"(r[0]), "=r"(r[1]), "=r"(r[2]), "=r"(r[3]) : "r"(addr));
}
__device__ __forceinline__ void cpa16u(uint32_t s, const void* g) {
    asm volatile("cp.async.cg.shared.global [%0], [%1], 16;\n" :: "r"(s), "l"(g));
}
__device__ __forceinline__ uint32_t smem_u32(const void* p) {
    return (uint32_t)__cvta_generic_to_shared(p);
}
__device__ __forceinline__ uint32_t pack_h2(float lo, float hi) {
    __half2 h = __floats2half2_rn(lo, hi);
    return *(uint32_t*)&h;
}

// ---------------------------------------------------------------------------
// prep kernels
// ---------------------------------------------------------------------------
__global__ void convert_half_kernel(const float* __restrict__ in,
                                    __half* __restrict__ out, int n4)
{
    int i = blockIdx.x * blockDim.x + threadIdx.x;
    if (i >= n4) return;
    float4 v = ((const float4*)in)[i];
    ((__half2*)out)[i * 2]     = __floats2half2_rn(v.x, v.y);
    ((__half2*)out)[i * 2 + 1] = __floats2half2_rn(v.z, v.w);
}

__global__ void transpose_half_kernel(const float* __restrict__ in,
                                      __half* __restrict__ out, int R, int C)
{
    __shared__ float tile[32][33];
    int c0 = blockIdx.x * 32, r0 = blockIdx.y * 32;
    int tx = threadIdx.x, ty = threadIdx.y;
#pragma unroll
    for (int i = 0; i < 32; i += 8)
        tile[ty + i][tx] = in[(size_t)(r0 + ty + i) * C + c0 + tx];
    __syncthreads();
#pragma unroll
    for (int i = 0; i < 32; i += 8)
        out[(size_t)(c0 + ty + i) * R + r0 + tx] = __float2half(tile[tx][ty + i]);
}

__global__ void rope_table_kernel()
{
    int idx = blockIdx.x * blockDim.x + threadIdx.x;
    if (idx >= S_LEN * 64) return;
    int i = idx & 63;
    int s = idx >> 6;
    double invf_d = pow(10000.0, -(double)(2 * i) / 128.0);
    float invf_f  = (float)invf_d;
    float ang_f   = (float)s * invf_f;
    double ds, dc;
    sincos((double)ang_f, &ds, &dc);
    g_cos[idx] = (float)dc;
    g_sin[idx] = (float)ds;
}

__global__ void rope_apply_kernel(__half* __restrict__ qkv)
{
    int idx = blockIdx.x * blockDim.x + threadIdx.x;
    int j = idx & 63;
    int h = (idx >> 6) & 15;
    int s = idx >> 10;
    if (s >= S_LEN) return;
    float c  = g_cos[s * 64 + j];
    float sn = g_sin[s * 64 + j];
    __half* q = qkv + (size_t)s * QKV_N + h * HDIM + j;
    __half* k = q + HID;
    float q1 = __half2float(q[0]), q2 = __half2float(q[64]);
    q[0]  = __float2half(q1 * c - q2 * sn);
    q[64] = __float2half(q2 * c + q1 * sn);
    float k1 = __half2float(k[0]), k2 = __half2float(k[64]);
    k[0]  = __float2half(k1 * c - k2 * sn);
    k[64] = __float2half(k2 * c + k1 * sn);
}

// ---------------------------------------------------------------------------
// fp16 GEMM (exact round-10 champion): C[M,N] = A[M,K] @ Bt^T (+bias).
// Block 128x128x32, 8 warps (4Mx2N), warp 32x64. ldmatrix fragments,
// cp.async 2-stage. Smem rows = 16 data words + 4 pad (stride 20).
// ---------------------------------------------------------------------------
#define GW 20

template <bool HAS_BIAS, typename OutT>
__global__ __launch_bounds__(256) void gemm_fp16_kernel(
    const __half* __restrict__ A, const __half* __restrict__ Bt,
    const float* __restrict__ bias, OutT* __restrict__ C,
    int M, int N, int K)
{
    __shared__ __align__(16) uint32_t As[2][128 * GW];
    __shared__ __align__(16) uint32_t Bs[2][128 * GW];

    const int tid  = threadIdx.x;
    const int warp = tid >> 5;
    const int lane = tid & 31;
    const int wm = (warp >> 1) * 32;
    const int wn = (warp & 1) * 64;
    const int m0 = blockIdx.y * 128;
    const int n0 = blockIdx.x * 128;

    const int l8  = lane & 7, sel = lane >> 3;
    const int a_row = l8 + ((sel & 1) << 3), a_col = (sel >> 1) << 2;  // A-type
    const int b_row = l8 + ((sel >> 1) << 3), b_col = (sel & 1) << 2;  // B-type

    float acc[2][8][4];
#pragma unroll
    for (int i = 0; i < 2; i++)
#pragma unroll
        for (int j = 0; j < 8; j++)
#pragma unroll
            for (int c = 0; c < 4; c++) acc[i][j][c] = 0.f;

    const int row = tid >> 1;
    const int jb  = (tid & 1) * 2;

    auto load_stage = [&](int st, int kb) {
#pragma unroll
        for (int j = 0; j < 2; j++) {
            int ch = jb + j;
            cpa16u(smem_u32(&As[st][row * GW + ch * 4]),
                   A + (size_t)(m0 + row) * K + kb + ch * 8);
            cpa16u(smem_u32(&Bs[st][row * GW + ch * 4]),
                   Bt + (size_t)(n0 + row) * K + kb + ch * 8);
        }
        asm volatile("cp.async.commit_group;\n" ::);
    };

    const int nk = K / 32;
    load_stage(0, 0);

    for (int t = 0; t < nk; t++) {
        if (t + 1 < nk) {
            load_stage((t + 1) & 1, (t + 1) * 32);
            asm volatile("cp.async.wait_group 1;\n" ::);
        } else {
            asm volatile("cp.async.wait_group 0;\n" ::);
        }
        __syncthreads();
        const uint32_t* Asm = As[t & 1];
        const uint32_t* Bsm = Bs[t & 1];

#pragma unroll
        for (int step = 0; step < 2; step++) {
            uint32_t a[2][4];
#pragma unroll
            for (int mf = 0; mf < 2; mf++)
                ldsm_x4(a[mf], smem_u32(&Asm[(wm + mf * 16 + a_row) * GW + step * 8 + a_col]));
#pragma unroll
            for (int nfp = 0; nfp < 4; nfp++) {
                uint32_t b[4];
                ldsm_x4(b, smem_u32(&Bsm[(wn + nfp * 16 + b_row) * GW + step * 8 + b_col]));
                mma_fp16(acc[0][2 * nfp],     a[0], b);
                mma_fp16(acc[1][2 * nfp],     a[1], b);
                mma_fp16(acc[0][2 * nfp + 1], a[0], b + 2);
                mma_fp16(acc[1][2 * nfp + 1], a[1], b + 2);
            }
        }
        __syncthreads();
    }

    const int lr = lane >> 2, lc = lane & 3;
#pragma unroll
    for (int mf = 0; mf < 2; mf++)
#pragma unroll
        for (int nf = 0; nf < 8; nf++) {
            int r0i = m0 + wm + mf * 16 + lr;
            int col = n0 + wn + nf * 8 + 2 * lc;
            float v0 = acc[mf][nf][0], v1 = acc[mf][nf][1];
            float v2 = acc[mf][nf][2], v3 = acc[mf][nf][3];
            if (HAS_BIAS) {
                float b0 = bias[col], b1 = bias[col + 1];
                v0 += b0; v1 += b1; v2 += b0; v3 += b1;
            }
            if (sizeof(OutT) == 2) {
                *(__half2*)((__half*)C + (size_t)r0i * N + col) = __floats2half2_rn(v0, v1);
                *(__half2*)((__half*)C + (size_t)(r0i + 8) * N + col) = __floats2half2_rn(v2, v3);
            } else {
                float* c0p = (float*)C + (size_t)r0i * N + col;
                float* c1p = (float*)C + (size_t)(r0i + 8) * N + col;
                c0p[0] = v0; c0p[1] = v1;
                c1p[0] = v2; c1p[1] = v3;
            }
        }
}

// ---------------------------------------------------------------------------
// fp16 flash attention, causal. R10 structure; P passed to the PV mma
// directly in registers (m16n8 C-layout == m16n8k16 A-layout when packed
// as half2) — no P smem, no extra syncs. K/V double-buffered cp.async.
// ---------------------------------------------------------------------------
#define KW 68

__global__ __launch_bounds__(256) void flash_fp16_kernel(
    const __half* __restrict__ qkv, __half* __restrict__ ctx)
{
    __shared__ __align__(16) uint32_t Ks[2][32 * KW];   // 8704 B each
    __shared__ __align__(16) uint32_t Vs[2][32 * KW];   // 8704 B each

    const int tid  = threadIdx.x;
    const int warp = tid >> 5;
    const int lane = tid & 31;
    const int lr = lane >> 2;
    const int lc = lane & 3;
    const int qt = 15 - blockIdx.x;        // heavy tiles first
    const int h  = blockIdx.y;
    const int q0 = qt * 128;
    const float scale = 0.08838834764831845f;

    const int l8  = lane & 7, sel = lane >> 3;
    const int a_row = l8 + ((sel & 1) << 3), a_col = (sel >> 1) << 2;  // A/V-type
    const int b_row = l8 + ((sel >> 1) << 3), b_col = (sel & 1) << 2;  // B-type

    uint32_t qa[8][4];
    {
        const __half* Qb = qkv + (size_t)(q0 + warp * 16) * QKV_N + h * HDIM;
#pragma unroll
        for (int st = 0; st < 8; st++) {
            qa[st][0] = *(const uint32_t*)(Qb + (size_t)lr       * QKV_N + st * 16 + 2 * lc);
            qa[st][1] = *(const uint32_t*)(Qb + (size_t)(lr + 8) * QKV_N + st * 16 + 2 * lc);
            qa[st][2] = *(const uint32_t*)(Qb + (size_t)lr       * QKV_N + st * 16 + 2 * lc + 8);
            qa[st][3] = *(const uint32_t*)(Qb + (size_t)(lr + 8) * QKV_N + st * 16 + 2 * lc + 8);
        }
    }

    float o[16][4];
#pragma unroll
    for (int i = 0; i < 16; i++)
#pragma unroll
        for (int c = 0; c < 4; c++) o[i][c] = 0.f;
    float mA = -1e30f, mB = -1e30f, lA = 0.f, lB = 0.f;

    const int rowA = q0 + warp * 16 + lr;
    const int rowB = rowA + 8;
    const int rowMaxWarp = q0 + warp * 16 + 15;
    const int ntiles = qt * 4 + 4;

    auto load_tile = [&](int st, int jt) {
#pragma unroll
        for (int it = 0; it < 2; it++) {
            int id  = tid + it * 256;
            int key = id >> 4;
            int ch  = id & 15;
            const __half* Kg = qkv + (size_t)(jt * 32 + key) * QKV_N + HID + h * HDIM + ch * 8;
            cpa16u(smem_u32(&Ks[st][key * KW + ch * 4]), Kg);
            cpa16u(smem_u32(&Vs[st][key * KW + ch * 4]), Kg + HID);
        }
        asm volatile("cp.async.commit_group;\n" ::);
    };

    load_tile(0, 0);

    for (int j = 0; j < ntiles; j++) {
        asm volatile("cp.async.wait_group 0;\n" ::);
        __syncthreads();
        if (j + 1 < ntiles) load_tile((j + 1) & 1, j + 1);

        const uint32_t* Ksm = Ks[j & 1];
        const uint32_t* Vsm = Vs[j & 1];
        const bool active = (j * 32 <= rowMaxWarp);
        if (active) {
            float s[4][4];
#pragma unroll
            for (int nf = 0; nf < 4; nf++)
#pragma unroll
                for (int c = 0; c < 4; c++) s[nf][c] = 0.f;
#pragma unroll
            for (int st = 0; st < 8; st++) {
#pragma unroll
                for (int nfp = 0; nfp < 2; nfp++) {
                    uint32_t b[4];
                    ldsm_x4(b, smem_u32(&Ksm[(nfp * 16 + b_row) * KW + st * 8 + b_col]));
                    mma_fp16(s[2 * nfp],     qa[st], b);
                    mma_fp16(s[2 * nfp + 1], qa[st], b + 2);
                }
            }

#pragma unroll
            for (int nf = 0; nf < 4; nf++) {
                int col0 = j * 32 + nf * 8 + 2 * lc;
                s[nf][0] = (col0     > rowA) ? -1e30f : s[nf][0] * scale;
                s[nf][1] = (col0 + 1 > rowA) ? -1e30f : s[nf][1] * scale;
                s[nf][2] = (col0     > rowB) ? -1e30f : s[nf][2] * scale;
                s[nf][3] = (col0 + 1 > rowB) ? -1e30f : s[nf][3] * scale;
            }

            float tA = -1e30f, tB = -1e30f;
#pragma unroll
            for (int nf = 0; nf < 4; nf++) {
                tA = fmaxf(tA, fmaxf(s[nf][0], s[nf][1]));
                tB = fmaxf(tB, fmaxf(s[nf][2], s[nf][3]));
            }
            tA = fmaxf(tA, __shfl_xor_sync(0xffffffffu, tA, 1));
            tA = fmaxf(tA, __shfl_xor_sync(0xffffffffu, tA, 2));
            tB = fmaxf(tB, __shfl_xor_sync(0xffffffffu, tB, 1));
            tB = fmaxf(tB, __shfl_xor_sync(0xffffffffu, tB, 2));

            float mAn = fmaxf(mA, tA), mBn = fmaxf(mB, tB);
            float aA = __expf(mA - mAn), aB = __expf(mB - mBn);
            float sA = 0.f, sB = 0.f;
#pragma unroll
            for (int nf = 0; nf < 4; nf++) {
                s[nf][0] = __expf(s[nf][0] - mAn);
                s[nf][1] = __expf(s[nf][1] - mAn);
                s[nf][2] = __expf(s[nf][2] - mBn);
                s[nf][3] = __expf(s[nf][3] - mBn);
                sA += s[nf][0] + s[nf][1];
                sB += s[nf][2] + s[nf][3];
            }
            sA += __shfl_xor_sync(0xffffffffu, sA, 1);
            sA += __shfl_xor_sync(0xffffffffu, sA, 2);
            sB += __shfl_xor_sync(0xffffffffu, sB, 1);
            sB += __shfl_xor_sync(0xffffffffu, sB, 2);
            lA = lA * aA + sA;
            lB = lB * aB + sB;
            mA = mAn; mB = mBn;
#pragma unroll
            for (int nf = 0; nf < 16; nf++) {
                o[nf][0] *= aA; o[nf][1] *= aA;
                o[nf][2] *= aB; o[nf][3] *= aB;
            }

            // O += P V — P fragment built directly from score registers:
            // m16n8 C-layout == m16n8k16 A-layout (FA2 identity).
#pragma unroll
            for (int st = 0; st < 2; st++) {
                uint32_t pa[4];
                pa[0] = pack_h2(s[2 * st][0],     s[2 * st][1]);
                pa[1] = pack_h2(s[2 * st][2],     s[2 * st][3]);
                pa[2] = pack_h2(s[2 * st + 1][0], s[2 * st + 1][1]);
                pa[3] = pack_h2(s[2 * st + 1][2], s[2 * st + 1][3]);
#pragma unroll
                for (int nfp = 0; nfp < 8; nfp++) {
                    uint32_t b[4];
                    ldsm_x4_t(b, smem_u32(&Vsm[(st * 16 + a_row) * KW + nfp * 8 + a_col]));
                    mma_fp16(o[2 * nfp],     pa, b);
                    mma_fp16(o[2 * nfp + 1], pa, b + 2);
                }
            }
        }
    }

    float rA = 1.f / lA, rB = 1.f / lB;
#pragma unroll
    for (int nf = 0; nf < 16; nf++) {
        int col = h * HDIM + nf * 8 + 2 * lc;
        *(__half2*)(ctx + (size_t)rowA * HID + col) =
            __floats2half2_rn(o[nf][0] * rA, o[nf][1] * rA);
        *(__half2*)(ctx + (size_t)rowB * HID + col) =
            __floats2half2_rn(o[nf][2] * rB, o[nf][3] * rB);
    }
}

// ---------------------------------------------------------------------------
// launcher
// ---------------------------------------------------------------------------
extern "C" void kernel_launch(void* const* d_in, const int* in_sizes, int n_in,
                              void* d_out, int out_size)
{
    const float* hidden = nullptr;
    const float* w_qkv  = nullptr;
    const float* b_qkv  = nullptr;
    const float* w_proj = nullptr;
    for (int i = 0; i < n_in; i++) {
        long sz = in_sizes[i];
        const float* p = (const float*)d_in[i];
        if (sz == (long)HID * QKV_N)      w_qkv = p;
        else if (sz == (long)QKV_N)       b_qkv = p;
        else {
            if (!hidden) hidden = p; else w_proj = p;
        }
    }
    float* out = (float*)d_out;

    __half *qkv_h, *ctx_h, *hid_h, *w1t, *w2t;
    cudaGetSymbolAddress((void**)&qkv_h, g_qkv_h);
    cudaGetSymbolAddress((void**)&ctx_h, g_ctx_h);
    cudaGetSymbolAddress((void**)&hid_h, g_hid_h);
    cudaGetSymbolAddress((void**)&w1t,   g_w1t_h);
    cudaGetSymbolAddress((void**)&w2t,   g_w2t_h);

    rope_table_kernel<<<(S_LEN * 64) / 256, 256>>>();
    convert_half_kernel<<<(S_LEN * HID / 4) / 256, 256>>>(hidden, hid_h, S_LEN * HID / 4);
    transpose_half_kernel<<<dim3(QKV_N / 32, HID / 32), dim3(32, 8)>>>(w_qkv, w1t, HID, QKV_N);
    transpose_half_kernel<<<dim3(HID / 32, HID / 32), dim3(32, 8)>>>(w_proj, w2t, HID, HID);

    gemm_fp16_kernel<true, __half><<<dim3(QKV_N / 128, S_LEN / 128), 256>>>(
        hid_h, w1t, b_qkv, qkv_h, S_LEN, QKV_N, HID);
    rope_apply_kernel<<<(S_LEN * NHEAD * 64) / 256, 256>>>(qkv_h);
    flash_fp16_kernel<<<dim3(S_LEN / 128, NHEAD), 256>>>(qkv_h, ctx_h);
    gemm_fp16_kernel<false, float><<<dim3(HID / 128, S_LEN / 128), 256>>>(
        ctx_h, w2t, nullptr, out, S_LEN, HID, HID);
}

// round 15
// speedup vs baseline: 1.2642x; 1.0205x over previous
#include <cuda_runtime.h>
#include <cuda_fp16.h>
#include <cstdint>

// ---------------------------------------------------------------------------
// QWenAttention: B=1, S=2048, H=2048, NH=16, HD=128
//   qkv = hidden @ w_qkv + b_qkv; rope(q,k); ctx = causal_attn(q,k,v);
//   out = ctx @ w_proj
// fp16 mma.sync m16n8k16 (fp32 accum); ldmatrix fragments.
// GEMM: 128x128x32, 3-stage cp.async (dynamic smem 61,440B; register-neutral
// deepening of the validated R10/R13 2-stage geometry).
// Flash: R13 champion (FA2 P-fragment identity, no P smem).
// ---------------------------------------------------------------------------

#define S_LEN 2048
#define HID   2048
#define NHEAD 16
#define HDIM  128
#define QKV_N 6144

__device__ __align__(16) __half g_qkv_h[S_LEN * QKV_N];
__device__ __align__(16) __half g_ctx_h[S_LEN * HID];
__device__ __align__(16) __half g_hid_h[S_LEN * HID];
__device__ __align__(16) __half g_w1t_h[QKV_N * HID];   // [N,K]
__device__ __align__(16) __half g_w2t_h[HID * HID];     // [N,K]
__device__ __align__(16) float  g_cos[S_LEN * 64];
__device__ __align__(16) float  g_sin[S_LEN * 64];

// ---------------------------------------------------------------------------
// helpers
// ---------------------------------------------------------------------------
__device__ __forceinline__ void mma_fp16(float* c, const uint32_t* a, const uint32_t* b) {
    asm volatile(
        "mma.sync.aligned.m16n8k16.row.col.f32.f16.f16.f32 "
        "{%0,%1,%2,%3}, {%4,%5,%6,%7}, {%8,%9}, {%0,%1,%2,%3};\n"
        : "+f"(c[0]), "+f"(c[1]), "+f"(c[2]), "+f"(c[3])
        : "r"(a[0]), "r"(a[1]), "r"(a[2]), "r"(a[3]), "r"(b[0]), "r"(b[1]));
}
__device__ __forceinline__ void ldsm_x4(uint32_t* r, uint32_t addr) {
    asm volatile("ldmatrix.sync.aligned.m8n8.x4.shared.b16 {%0,%1,%2,%3}, [%4];"
        : "=r"(r[0]), "=r"(r[1]), "=r"(r[2]), "=r"(r[3]) : "r"(addr));
}
__device__ __forceinline__ void ldsm_x4_t(uint32_t* r, uint32_t addr) {
    asm volatile("ldmatrix.sync.aligned.m8n8.x4.trans.shared.b16 {%0,%1,%2,%3}, [%4];"
        : "=r"(r[0]), "=r"(r[1]), "=r"(r[2]), "=r"(r[3]) : "r"(addr));
}
__device__ __forceinline__ void cpa16u(uint32_t s, const void* g) {
    asm volatile("cp.async.cg.shared.global [%0], [%1], 16;\n" :: "r"(s), "l"(g));
}
__device__ __forceinline__ uint32_t smem_u32(const void* p) {
    return (uint32_t)__cvta_generic_to_shared(p);
}
__device__ __forceinline__ uint32_t pack_h2(float lo, float hi) {
    __half2 h = __floats2half2_rn(lo, hi);
    return *(uint32_t*)&h;
}

// ---------------------------------------------------------------------------
// prep kernels
// ---------------------------------------------------------------------------
__global__ void convert_half_kernel(const float* __restrict__ in,
                                    __half* __restrict__ out, int n4)
{
    int i = blockIdx.x * blockDim.x + threadIdx.x;
    if (i >= n4) return;
    float4 v = ((const float4*)in)[i];
    ((__half2*)out)[i * 2]     = __floats2half2_rn(v.x, v.y);
    ((__half2*)out)[i * 2 + 1] = __floats2half2_rn(v.z, v.w);
}

__global__ void transpose_half_kernel(const float* __restrict__ in,
                                      __half* __restrict__ out, int R, int C)
{
    __shared__ float tile[32][33];
    int c0 = blockIdx.x * 32, r0 = blockIdx.y * 32;
    int tx = threadIdx.x, ty = threadIdx.y;
#pragma unroll
    for (int i = 0; i < 32; i += 8)
        tile[ty + i][tx] = in[(size_t)(r0 + ty + i) * C + c0 + tx];
    __syncthreads();
#pragma unroll
    for (int i = 0; i < 32; i += 8)
        out[(size_t)(c0 + ty + i) * R + r0 + tx] = __float2half(tile[tx][ty + i]);
}

__global__ void rope_table_kernel()
{
    int idx = blockIdx.x * blockDim.x + threadIdx.x;
    if (idx >= S_LEN * 64) return;
    int i = idx & 63;
    int s = idx >> 6;
    double invf_d = pow(10000.0, -(double)(2 * i) / 128.0);
    float invf_f  = (float)invf_d;
    float ang_f   = (float)s * invf_f;
    double ds, dc;
    sincos((double)ang_f, &ds, &dc);
    g_cos[idx] = (float)dc;
    g_sin[idx] = (float)ds;
}

__global__ void rope_apply_kernel(__half* __restrict__ qkv)
{
    int idx = blockIdx.x * blockDim.x + threadIdx.x;
    int j = idx & 63;
    int h = (idx >> 6) & 15;
    int s = idx >> 10;
    if (s >= S_LEN) return;
    float c  = g_cos[s * 64 + j];
    float sn = g_sin[s * 64 + j];
    __half* q = qkv + (size_t)s * QKV_N + h * HDIM + j;
    __half* k = q + HID;
    float q1 = __half2float(q[0]), q2 = __half2float(q[64]);
    q[0]  = __float2half(q1 * c - q2 * sn);
    q[64] = __float2half(q2 * c + q1 * sn);
    float k1 = __half2float(k[0]), k2 = __half2float(k[64]);
    k[0]  = __float2half(k1 * c - k2 * sn);
    k[64] = __float2half(k2 * c + k1 * sn);
}

// ---------------------------------------------------------------------------
// fp16 GEMM: C[M,N] = A[M,K] @ Bt^T (+bias); A [M,K], Bt [N,K] half.
// Block 128x128x32, 8 warps (4Mx2N), warp 32x64. ldmatrix fragments,
// cp.async 3-STAGE pipeline (dynamic smem). Smem rows: 16 data + 4 pad words.
// ---------------------------------------------------------------------------
#define GW 20
#define GSTG (128 * GW)                         // words per stage (A or B)
#define GEMM_SMEM_BYTES (6 * GSTG * 4)          // 61,440 B

template <bool HAS_BIAS, typename OutT>
__global__ __launch_bounds__(256) void gemm_fp16_kernel(
    const __half* __restrict__ A, const __half* __restrict__ Bt,
    const float* __restrict__ bias, OutT* __restrict__ C,
    int M, int N, int K)
{
    extern __shared__ __align__(16) uint32_t pool[];
    // As stage st: pool + st*GSTG ; Bs stage st: pool + (3+st)*GSTG

    const int tid  = threadIdx.x;
    const int warp = tid >> 5;
    const int lane = tid & 31;
    const int wm = (warp >> 1) * 32;
    const int wn = (warp & 1) * 64;
    const int m0 = blockIdx.y * 128;
    const int n0 = blockIdx.x * 128;

    const int l8  = lane & 7, sel = lane >> 3;
    const int a_row = l8 + ((sel & 1) << 3), a_col = (sel >> 1) << 2;  // A-type
    const int b_row = l8 + ((sel >> 1) << 3), b_col = (sel & 1) << 2;  // B-type

    float acc[2][8][4];
#pragma unroll
    for (int i = 0; i < 2; i++)
#pragma unroll
        for (int j = 0; j < 8; j++)
#pragma unroll
            for (int c = 0; c < 4; c++) acc[i][j][c] = 0.f;

    const int row = tid >> 1;
    const int jb  = (tid & 1) * 2;

    auto load_stage = [&](int st, int kb) {
        uint32_t* As = pool + st * GSTG;
        uint32_t* Bs = pool + (3 + st) * GSTG;
#pragma unroll
        for (int j = 0; j < 2; j++) {
            int ch = jb + j;
            cpa16u(smem_u32(&As[row * GW + ch * 4]),
                   A + (size_t)(m0 + row) * K + kb + ch * 8);
            cpa16u(smem_u32(&Bs[row * GW + ch * 4]),
                   Bt + (size_t)(n0 + row) * K + kb + ch * 8);
        }
        asm volatile("cp.async.commit_group;\n" ::);
    };

    const int nk = K / 32;
    load_stage(0, 0);
    load_stage(1, 32);

    for (int t = 0; t < nk; t++) {
        if (t + 2 < nk) asm volatile("cp.async.wait_group 1;\n" ::);
        else            asm volatile("cp.async.wait_group 0;\n" ::);
        __syncthreads();
        if (t + 2 < nk) load_stage((t + 2) % 3, (t + 2) * 32);

        const uint32_t* Asm = pool + (t % 3) * GSTG;
        const uint32_t* Bsm = pool + (3 + (t % 3)) * GSTG;

#pragma unroll
        for (int step = 0; step < 2; step++) {
            uint32_t a[2][4];
#pragma unroll
            for (int mf = 0; mf < 2; mf++)
                ldsm_x4(a[mf], smem_u32(&Asm[(wm + mf * 16 + a_row) * GW + step * 8 + a_col]));
#pragma unroll
            for (int nfp = 0; nfp < 4; nfp++) {
                uint32_t b[4];
                ldsm_x4(b, smem_u32(&Bsm[(wn + nfp * 16 + b_row) * GW + step * 8 + b_col]));
                mma_fp16(acc[0][2 * nfp],     a[0], b);
                mma_fp16(acc[1][2 * nfp],     a[1], b);
                mma_fp16(acc[0][2 * nfp + 1], a[0], b + 2);
                mma_fp16(acc[1][2 * nfp + 1], a[1], b + 2);
            }
        }
    }

    const int lr = lane >> 2, lc = lane & 3;
#pragma unroll
    for (int mf = 0; mf < 2; mf++)
#pragma unroll
        for (int nf = 0; nf < 8; nf++) {
            int r0i = m0 + wm + mf * 16 + lr;
            int col = n0 + wn + nf * 8 + 2 * lc;
            float v0 = acc[mf][nf][0], v1 = acc[mf][nf][1];
            float v2 = acc[mf][nf][2], v3 = acc[mf][nf][3];
            if (HAS_BIAS) {
                float b0 = bias[col], b1 = bias[col + 1];
                v0 += b0; v1 += b1; v2 += b0; v3 += b1;
            }
            if (sizeof(OutT) == 2) {
                *(__half2*)((__half*)C + (size_t)r0i * N + col) = __floats2half2_rn(v0, v1);
                *(__half2*)((__half*)C + (size_t)(r0i + 8) * N + col) = __floats2half2_rn(v2, v3);
            } else {
                float* c0p = (float*)C + (size_t)r0i * N + col;
                float* c1p = (float*)C + (size_t)(r0i + 8) * N + col;
                c0p[0] = v0; c0p[1] = v1;
                c1p[0] = v2; c1p[1] = v3;
            }
        }
}

// ---------------------------------------------------------------------------
// fp16 flash attention, causal (R13 champion — FA2 P identity, no P smem).
// ---------------------------------------------------------------------------
#define KW 68

__global__ __launch_bounds__(256) void flash_fp16_kernel(
    const __half* __restrict__ qkv, __half* __restrict__ ctx)
{
    __shared__ __align__(16) uint32_t Ks[2][32 * KW];
    __shared__ __align__(16) uint32_t Vs[2][32 * KW];

    const int tid  = threadIdx.x;
    const int warp = tid >> 5;
    const int lane = tid & 31;
    const int lr = lane >> 2;
    const int lc = lane & 3;
    const int qt = 15 - blockIdx.x;
    const int h  = blockIdx.y;
    const int q0 = qt * 128;
    const float scale = 0.08838834764831845f;

    const int l8  = lane & 7, sel = lane >> 3;
    const int a_row = l8 + ((sel & 1) << 3), a_col = (sel >> 1) << 2;
    const int b_row = l8 + ((sel >> 1) << 3), b_col = (sel & 1) << 2;

    uint32_t qa[8][4];
    {
        const __half* Qb = qkv + (size_t)(q0 + warp * 16) * QKV_N + h * HDIM;
#pragma unroll
        for (int st = 0; st < 8; st++) {
            qa[st][0] = *(const uint32_t*)(Qb + (size_t)lr       * QKV_N + st * 16 + 2 * lc);
            qa[st][1] = *(const uint32_t*)(Qb + (size_t)(lr + 8) * QKV_N + st * 16 + 2 * lc);
            qa[st][2] = *(const uint32_t*)(Qb + (size_t)lr       * QKV_N + st * 16 + 2 * lc + 8);
            qa[st][3] = *(const uint32_t*)(Qb + (size_t)(lr + 8) * QKV_N + st * 16 + 2 * lc + 8);
        }
    }

    float o[16][4];
#pragma unroll
    for (int i = 0; i < 16; i++)
#pragma unroll
        for (int c = 0; c < 4; c++) o[i][c] = 0.f;
    float mA = -1e30f, mB = -1e30f, lA = 0.f, lB = 0.f;

    const int rowA = q0 + warp * 16 + lr;
    const int rowB = rowA + 8;
    const int rowMaxWarp = q0 + warp * 16 + 15;
    const int ntiles = qt * 4 + 4;

    auto load_tile = [&](int st, int jt) {
#pragma unroll
        for (int it = 0; it < 2; it++) {
            int id  = tid + it * 256;
            int key = id >> 4;
            int ch  = id & 15;
            const __half* Kg = qkv + (size_t)(jt * 32 + key) * QKV_N + HID + h * HDIM + ch * 8;
            cpa16u(smem_u32(&Ks[st][key * KW + ch * 4]), Kg);
            cpa16u(smem_u32(&Vs[st][key * KW + ch * 4]), Kg + HID);
        }
        asm volatile("cp.async.commit_group;\n" ::);
    };

    load_tile(0, 0);

    for (int j = 0; j < ntiles; j++) {
        asm volatile("cp.async.wait_group 0;\n" ::);
        __syncthreads();
        if (j + 1 < ntiles) load_tile((j + 1) & 1, j + 1);

        const uint32_t* Ksm = Ks[j & 1];
        const uint32_t* Vsm = Vs[j & 1];
        const bool active = (j * 32 <= rowMaxWarp);
        if (active) {
            float s[4][4];
#pragma unroll
            for (int nf = 0; nf < 4; nf++)
#pragma unroll
                for (int c = 0; c < 4; c++) s[nf][c] = 0.f;
#pragma unroll
            for (int st = 0; st < 8; st++) {
#pragma unroll
                for (int nfp = 0; nfp < 2; nfp++) {
                    uint32_t b[4];
                    ldsm_x4(b, smem_u32(&Ksm[(nfp * 16 + b_row) * KW + st * 8 + b_col]));
                    mma_fp16(s[2 * nfp],     qa[st], b);
                    mma_fp16(s[2 * nfp + 1], qa[st], b + 2);
                }
            }

#pragma unroll
            for (int nf = 0; nf < 4; nf++) {
                int col0 = j * 32 + nf * 8 + 2 * lc;
                s[nf][0] = (col0     > rowA) ? -1e30f : s[nf][0] * scale;
                s[nf][1] = (col0 + 1 > rowA) ? -1e30f : s[nf][1] * scale;
                s[nf][2] = (col0     > rowB) ? -1e30f : s[nf][2] * scale;
                s[nf][3] = (col0 + 1 > rowB) ? -1e30f : s[nf][3] * scale;
            }

            float tA = -1e30f, tB = -1e30f;
#pragma unroll
            for (int nf = 0; nf < 4; nf++) {
                tA = fmaxf(tA, fmaxf(s[nf][0], s[nf][1]));
                tB = fmaxf(tB, fmaxf(s[nf][2], s[nf][3]));
            }
            tA = fmaxf(tA, __shfl_xor_sync(0xffffffffu, tA, 1));
            tA = fmaxf(tA, __shfl_xor_sync(0xffffffffu, tA, 2));
            tB = fmaxf(tB, __shfl_xor_sync(0xffffffffu, tB, 1));
            tB = fmaxf(tB, __shfl_xor_sync(0xffffffffu, tB, 2));

            float mAn = fmaxf(mA, tA), mBn = fmaxf(mB, tB);
            float aA = __expf(mA - mAn), aB = __expf(mB - mBn);
            float sA = 0.f, sB = 0.f;
#pragma unroll
            for (int nf = 0; nf < 4; nf++) {
                s[nf][0] = __expf(s[nf][0] - mAn);
                s[nf][1] = __expf(s[nf][1] - mAn);
                s[nf][2] = __expf(s[nf][2] - mBn);
                s[nf][3] = __expf(s[nf][3] - mBn);
                sA += s[nf][0] + s[nf][1];
                sB += s[nf][2] + s[nf][3];
            }
            sA += __shfl_xor_sync(0xffffffffu, sA, 1);
            sA += __shfl_xor_sync(0xffffffffu, sA, 2);
            sB += __shfl_xor_sync(0xffffffffu, sB, 1);
            sB += __shfl_xor_sync(0xffffffffu, sB, 2);
            lA = lA * aA + sA;
            lB = lB * aB + sB;
            mA = mAn; mB = mBn;
#pragma unroll
            for (int nf = 0; nf < 16; nf++) {
                o[nf][0] *= aA; o[nf][1] *= aA;
                o[nf][2] *= aB; o[nf][3] *= aB;
            }

#pragma unroll
            for (int st = 0; st < 2; st++) {
                uint32_t pa[4];
                pa[0] = pack_h2(s[2 * st][0],     s[2 * st][1]);
                pa[1] = pack_h2(s[2 * st][2],     s[2 * st][3]);
                pa[2] = pack_h2(s[2 * st + 1][0], s[2 * st + 1][1]);
                pa[3] = pack_h2(s[2 * st + 1][2], s[2 * st + 1][3]);
#pragma unroll
                for (int nfp = 0; nfp < 8; nfp++) {
                    uint32_t b[4];
                    ldsm_x4_t(b, smem_u32(&Vsm[(st * 16 + a_row) * KW + nfp * 8 + a_col]));
                    mma_fp16(o[2 * nfp],     pa, b);
                    mma_fp16(o[2 * nfp + 1], pa, b + 2);
                }
            }
        }
    }

    float rA = 1.f / lA, rB = 1.f / lB;
#pragma unroll
    for (int nf = 0; nf < 16; nf++) {
        int col = h * HDIM + nf * 8 + 2 * lc;
        *(__half2*)(ctx + (size_t)rowA * HID + col) =
            __floats2half2_rn(o[nf][0] * rA, o[nf][1] * rA);
        *(__half2*)(ctx + (size_t)rowB * HID + col) =
            __floats2half2_rn(o[nf][2] * rB, o[nf][3] * rB);
    }
}

// ---------------------------------------------------------------------------
// launcher
// ---------------------------------------------------------------------------
extern "C" void kernel_launch(void* const* d_in, const int* in_sizes, int n_in,
                              void* d_out, int out_size)
{
    const float* hidden = nullptr;
    const float* w_qkv  = nullptr;
    const float* b_qkv  = nullptr;
    const float* w_proj = nullptr;
    for (int i = 0; i < n_in; i++) {
        long sz = in_sizes[i];
        const float* p = (const float*)d_in[i];
        if (sz == (long)HID * QKV_N)      w_qkv = p;
        else if (sz == (long)QKV_N)       b_qkv = p;
        else {
            if (!hidden) hidden = p; else w_proj = p;
        }
    }
    float* out = (float*)d_out;

    __half *qkv_h, *ctx_h, *hid_h, *w1t, *w2t;
    cudaGetSymbolAddress((void**)&qkv_h, g_qkv_h);
    cudaGetSymbolAddress((void**)&ctx_h, g_ctx_h);
    cudaGetSymbolAddress((void**)&hid_h, g_hid_h);
    cudaGetSymbolAddress((void**)&w1t,   g_w1t_h);
    cudaGetSymbolAddress((void**)&w2t,   g_w2t_h);

    cudaFuncSetAttribute(gemm_fp16_kernel<true, __half>,
                         cudaFuncAttributeMaxDynamicSharedMemorySize, GEMM_SMEM_BYTES);
    cudaFuncSetAttribute(gemm_fp16_kernel<false, float>,
                         cudaFuncAttributeMaxDynamicSharedMemorySize, GEMM_SMEM_BYTES);

    rope_table_kernel<<<(S_LEN * 64) / 256, 256>>>();
    convert_half_kernel<<<(S_LEN * HID / 4) / 256, 256>>>(hidden, hid_h, S_LEN * HID / 4);
    transpose_half_kernel<<<dim3(QKV_N / 32, HID / 32), dim3(32, 8)>>>(w_qkv, w1t, HID, QKV_N);
    transpose_half_kernel<<<dim3(HID / 32, HID / 32), dim3(32, 8)>>>(w_proj, w2t, HID, HID);

    gemm_fp16_kernel<true, __half>
        <<<dim3(QKV_N / 128, S_LEN / 128), 256, GEMM_SMEM_BYTES>>>(
        hid_h, w1t, b_qkv, qkv_h, S_LEN, QKV_N, HID);
    rope_apply_kernel<<<(S_LEN * NHEAD * 64) / 256, 256>>>(qkv_h);
    flash_fp16_kernel<<<dim3(S_LEN / 128, NHEAD), 256>>>(qkv_h, ctx_h);
    gemm_fp16_kernel<false, float>
        <<<dim3(HID / 128, S_LEN / 128), 256, GEMM_SMEM_BYTES>>>(
        ctx_h, w2t, nullptr, out, S_LEN, HID, HID);
}

// round 16
// speedup vs baseline: 1.3078x; 1.0345x over previous
#include <cuda_runtime.h>
#include <cuda_fp16.h>
#include <cstdint>

// ---------------------------------------------------------------------------
// QWenAttention: B=1, S=2048, H=2048, NH=16, HD=128
//   qkv = hidden @ w_qkv + b_qkv; rope(q,k); ctx = causal_attn(q,k,v);
//   out = ctx @ w_proj
// fp16 mma.sync m16n8k16 (fp32 accum); ldmatrix fragments.
// GEMM: 128x128x32, 3-stage cp.async (R14 champion, unchanged).
// Flash: 64-KEY tiles (halved softmax/rescale overhead per key), dynamic
// smem, FA2 P-fragment identity.
// ---------------------------------------------------------------------------

#define S_LEN 2048
#define HID   2048
#define NHEAD 16
#define HDIM  128
#define QKV_N 6144

__device__ __align__(16) __half g_qkv_h[S_LEN * QKV_N];
__device__ __align__(16) __half g_ctx_h[S_LEN * HID];
__device__ __align__(16) __half g_hid_h[S_LEN * HID];
__device__ __align__(16) __half g_w1t_h[QKV_N * HID];   // [N,K]
__device__ __align__(16) __half g_w2t_h[HID * HID];     // [N,K]
__device__ __align__(16) float  g_cos[S_LEN * 64];
__device__ __align__(16) float  g_sin[S_LEN * 64];

// ---------------------------------------------------------------------------
// helpers
// ---------------------------------------------------------------------------
__device__ __forceinline__ void mma_fp16(float* c, const uint32_t* a, const uint32_t* b) {
    asm volatile(
        "mma.sync.aligned.m16n8k16.row.col.f32.f16.f16.f32 "
        "{%0,%1,%2,%3}, {%4,%5,%6,%7}, {%8,%9}, {%0,%1,%2,%3};\n"
        : "+f"(c[0]), "+f"(c[1]), "+f"(c[2]), "+f"(c[3])
        : "r"(a[0]), "r"(a[1]), "r"(a[2]), "r"(a[3]), "r"(b[0]), "r"(b[1]));
}
__device__ __forceinline__ void ldsm_x4(uint32_t* r, uint32_t addr) {
    asm volatile("ldmatrix.sync.aligned.m8n8.x4.shared.b16 {%0,%1,%2,%3}, [%4];"
        : "=r"(r[0]), "=r"(r[1]), "=r"(r[2]), "=r"(r[3]) : "r"(addr));
}
__device__ __forceinline__ void ldsm_x4_t(uint32_t* r, uint32_t addr) {
    asm volatile("ldmatrix.sync.aligned.m8n8.x4.trans.shared.b16 {%0,%1,%2,%3}, [%4];"
        : "=r"(r[0]), "=r"(r[1]), "=r"(r[2]), "=r"(r[3]) : "r"(addr));
}
__device__ __forceinline__ void cpa16u(uint32_t s, const void* g) {
    asm volatile("cp.async.cg.shared.global [%0], [%1], 16;\n" :: "r"(s), "l"(g));
}
__device__ __forceinline__ uint32_t smem_u32(const void* p) {
    return (uint32_t)__cvta_generic_to_shared(p);
}
__device__ __forceinline__ uint32_t pack_h2(float lo, float hi) {
    __half2 h = __floats2half2_rn(lo, hi);
    return *(uint32_t*)&h;
}

// ---------------------------------------------------------------------------
// prep kernels
// ---------------------------------------------------------------------------
__global__ void convert_half_kernel(const float* __restrict__ in,
                                    __half* __restrict__ out, int n4)
{
    int i = blockIdx.x * blockDim.x + threadIdx.x;
    if (i >= n4) return;
    float4 v = ((const float4*)in)[i];
    ((__half2*)out)[i * 2]     = __floats2half2_rn(v.x, v.y);
    ((__half2*)out)[i * 2 + 1] = __floats2half2_rn(v.z, v.w);
}

__global__ void transpose_half_kernel(const float* __restrict__ in,
                                      __half* __restrict__ out, int R, int C)
{
    __shared__ float tile[32][33];
    int c0 = blockIdx.x * 32, r0 = blockIdx.y * 32;
    int tx = threadIdx.x, ty = threadIdx.y;
#pragma unroll
    for (int i = 0; i < 32; i += 8)
        tile[ty + i][tx] = in[(size_t)(r0 + ty + i) * C + c0 + tx];
    __syncthreads();
#pragma unroll
    for (int i = 0; i < 32; i += 8)
        out[(size_t)(c0 + ty + i) * R + r0 + tx] = __float2half(tile[tx][ty + i]);
}

__global__ void rope_table_kernel()
{
    int idx = blockIdx.x * blockDim.x + threadIdx.x;
    if (idx >= S_LEN * 64) return;
    int i = idx & 63;
    int s = idx >> 6;
    double invf_d = pow(10000.0, -(double)(2 * i) / 128.0);
    float invf_f  = (float)invf_d;
    float ang_f   = (float)s * invf_f;
    double ds, dc;
    sincos((double)ang_f, &ds, &dc);
    g_cos[idx] = (float)dc;
    g_sin[idx] = (float)ds;
}

__global__ void rope_apply_kernel(__half* __restrict__ qkv)
{
    int idx = blockIdx.x * blockDim.x + threadIdx.x;
    int j = idx & 63;
    int h = (idx >> 6) & 15;
    int s = idx >> 10;
    if (s >= S_LEN) return;
    float c  = g_cos[s * 64 + j];
    float sn = g_sin[s * 64 + j];
    __half* q = qkv + (size_t)s * QKV_N + h * HDIM + j;
    __half* k = q + HID;
    float q1 = __half2float(q[0]), q2 = __half2float(q[64]);
    q[0]  = __float2half(q1 * c - q2 * sn);
    q[64] = __float2half(q2 * c + q1 * sn);
    float k1 = __half2float(k[0]), k2 = __half2float(k[64]);
    k[0]  = __float2half(k1 * c - k2 * sn);
    k[64] = __float2half(k2 * c + k1 * sn);
}

// ---------------------------------------------------------------------------
// fp16 GEMM (R14 champion): 128x128x32, 3-stage cp.async, dynamic smem.
// ---------------------------------------------------------------------------
#define GW 20
#define GSTG (128 * GW)
#define GEMM_SMEM_BYTES (6 * GSTG * 4)          // 61,440 B

template <bool HAS_BIAS, typename OutT>
__global__ __launch_bounds__(256) void gemm_fp16_kernel(
    const __half* __restrict__ A, const __half* __restrict__ Bt,
    const float* __restrict__ bias, OutT* __restrict__ C,
    int M, int N, int K)
{
    extern __shared__ __align__(16) uint32_t pool[];

    const int tid  = threadIdx.x;
    const int warp = tid >> 5;
    const int lane = tid & 31;
    const int wm = (warp >> 1) * 32;
    const int wn = (warp & 1) * 64;
    const int m0 = blockIdx.y * 128;
    const int n0 = blockIdx.x * 128;

    const int l8  = lane & 7, sel = lane >> 3;
    const int a_row = l8 + ((sel & 1) << 3), a_col = (sel >> 1) << 2;
    const int b_row = l8 + ((sel >> 1) << 3), b_col = (sel & 1) << 2;

    float acc[2][8][4];
#pragma unroll
    for (int i = 0; i < 2; i++)
#pragma unroll
        for (int j = 0; j < 8; j++)
#pragma unroll
            for (int c = 0; c < 4; c++) acc[i][j][c] = 0.f;

    const int row = tid >> 1;
    const int jb  = (tid & 1) * 2;

    auto load_stage = [&](int st, int kb) {
        uint32_t* As = pool + st * GSTG;
        uint32_t* Bs = pool + (3 + st) * GSTG;
#pragma unroll
        for (int j = 0; j < 2; j++) {
            int ch = jb + j;
            cpa16u(smem_u32(&As[row * GW + ch * 4]),
                   A + (size_t)(m0 + row) * K + kb + ch * 8);
            cpa16u(smem_u32(&Bs[row * GW + ch * 4]),
                   Bt + (size_t)(n0 + row) * K + kb + ch * 8);
        }
        asm volatile("cp.async.commit_group;\n" ::);
    };

    const int nk = K / 32;
    load_stage(0, 0);
    load_stage(1, 32);

    for (int t = 0; t < nk; t++) {
        if (t + 2 < nk) asm volatile("cp.async.wait_group 1;\n" ::);
        else            asm volatile("cp.async.wait_group 0;\n" ::);
        __syncthreads();
        if (t + 2 < nk) load_stage((t + 2) % 3, (t + 2) * 32);

        const uint32_t* Asm = pool + (t % 3) * GSTG;
        const uint32_t* Bsm = pool + (3 + (t % 3)) * GSTG;

#pragma unroll
        for (int step = 0; step < 2; step++) {
            uint32_t a[2][4];
#pragma unroll
            for (int mf = 0; mf < 2; mf++)
                ldsm_x4(a[mf], smem_u32(&Asm[(wm + mf * 16 + a_row) * GW + step * 8 + a_col]));
#pragma unroll
            for (int nfp = 0; nfp < 4; nfp++) {
                uint32_t b[4];
                ldsm_x4(b, smem_u32(&Bsm[(wn + nfp * 16 + b_row) * GW + step * 8 + b_col]));
                mma_fp16(acc[0][2 * nfp],     a[0], b);
                mma_fp16(acc[1][2 * nfp],     a[1], b);
                mma_fp16(acc[0][2 * nfp + 1], a[0], b + 2);
                mma_fp16(acc[1][2 * nfp + 1], a[1], b + 2);
            }
        }
    }

    const int lr = lane >> 2, lc = lane & 3;
#pragma unroll
    for (int mf = 0; mf < 2; mf++)
#pragma unroll
        for (int nf = 0; nf < 8; nf++) {
            int r0i = m0 + wm + mf * 16 + lr;
            int col = n0 + wn + nf * 8 + 2 * lc;
            float v0 = acc[mf][nf][0], v1 = acc[mf][nf][1];
            float v2 = acc[mf][nf][2], v3 = acc[mf][nf][3];
            if (HAS_BIAS) {
                float b0 = bias[col], b1 = bias[col + 1];
                v0 += b0; v1 += b1; v2 += b0; v3 += b1;
            }
            if (sizeof(OutT) == 2) {
                *(__half2*)((__half*)C + (size_t)r0i * N + col) = __floats2half2_rn(v0, v1);
                *(__half2*)((__half*)C + (size_t)(r0i + 8) * N + col) = __floats2half2_rn(v2, v3);
            } else {
                float* c0p = (float*)C + (size_t)r0i * N + col;
                float* c1p = (float*)C + (size_t)(r0i + 8) * N + col;
                c0p[0] = v0; c0p[1] = v1;
                c1p[0] = v2; c1p[1] = v3;
            }
        }
}

// ---------------------------------------------------------------------------
// fp16 flash attention, causal. 128 queries x 1 head, 8 warps (16 rows).
// 64-KEY tiles (softmax overhead halved per key), cp.async double-buffered
// K/V in DYNAMIC smem, FA2 P-fragment identity (no P smem).
// ---------------------------------------------------------------------------
#define KW 68
#define FSTG (64 * KW)                          // words per K or V stage
#define FLASH_SMEM_BYTES (4 * FSTG * 4)         // 69,632 B

__global__ __launch_bounds__(256) void flash_fp16_kernel(
    const __half* __restrict__ qkv, __half* __restrict__ ctx)
{
    extern __shared__ __align__(16) uint32_t fpool[];
    // Ks stage st: fpool + st*FSTG ; Vs stage st: fpool + (2+st)*FSTG

    const int tid  = threadIdx.x;
    const int warp = tid >> 5;
    const int lane = tid & 31;
    const int lr = lane >> 2;
    const int lc = lane & 3;
    const int qt = 15 - blockIdx.x;        // heavy tiles first
    const int h  = blockIdx.y;
    const int q0 = qt * 128;
    const float scale = 0.08838834764831845f;

    const int l8  = lane & 7, sel = lane >> 3;
    const int a_row = l8 + ((sel & 1) << 3), a_col = (sel >> 1) << 2;  // A/V-type
    const int b_row = l8 + ((sel >> 1) << 3), b_col = (sel & 1) << 2;  // B-type

    uint32_t qa[8][4];
    {
        const __half* Qb = qkv + (size_t)(q0 + warp * 16) * QKV_N + h * HDIM;
#pragma unroll
        for (int st = 0; st < 8; st++) {
            qa[st][0] = *(const uint32_t*)(Qb + (size_t)lr       * QKV_N + st * 16 + 2 * lc);
            qa[st][1] = *(const uint32_t*)(Qb + (size_t)(lr + 8) * QKV_N + st * 16 + 2 * lc);
            qa[st][2] = *(const uint32_t*)(Qb + (size_t)lr       * QKV_N + st * 16 + 2 * lc + 8);
            qa[st][3] = *(const uint32_t*)(Qb + (size_t)(lr + 8) * QKV_N + st * 16 + 2 * lc + 8);
        }
    }

    float o[16][4];
#pragma unroll
    for (int i = 0; i < 16; i++)
#pragma unroll
        for (int c = 0; c < 4; c++) o[i][c] = 0.f;
    float mA = -1e30f, mB = -1e30f, lA = 0.f, lB = 0.f;

    const int rowA = q0 + warp * 16 + lr;
    const int rowB = rowA + 8;
    const int rowMaxWarp = q0 + warp * 16 + 15;
    const int ntiles = 2 * qt + 2;          // 64-key tiles

    auto load_tile = [&](int st, int jt) {
        uint32_t* Ks = fpool + st * FSTG;
        uint32_t* Vs = fpool + (2 + st) * FSTG;
#pragma unroll
        for (int it = 0; it < 4; it++) {
            int id  = tid + it * 256;       // 0..1023
            int key = id >> 4;              // 0..63
            int ch  = id & 15;
            const __half* Kg = qkv + (size_t)(jt * 64 + key) * QKV_N + HID + h * HDIM + ch * 8;
            cpa16u(smem_u32(&Ks[key * KW + ch * 4]), Kg);
            cpa16u(smem_u32(&Vs[key * KW + ch * 4]), Kg + HID);
        }
        asm volatile("cp.async.commit_group;\n" ::);
    };

    load_tile(0, 0);

    for (int j = 0; j < ntiles; j++) {
        asm volatile("cp.async.wait_group 0;\n" ::);
        __syncthreads();
        if (j + 1 < ntiles) load_tile((j + 1) & 1, j + 1);

        const uint32_t* Ksm = fpool + (j & 1) * FSTG;
        const uint32_t* Vsm = fpool + (2 + (j & 1)) * FSTG;
        const bool active = (j * 64 <= rowMaxWarp);
        if (active) {
            // S = Q K^T (16 x 64 per warp)
            float s[8][4];
#pragma unroll
            for (int nf = 0; nf < 8; nf++)
#pragma unroll
                for (int c = 0; c < 4; c++) s[nf][c] = 0.f;
#pragma unroll
            for (int st = 0; st < 8; st++) {
#pragma unroll
                for (int nfp = 0; nfp < 4; nfp++) {
                    uint32_t b[4];
                    ldsm_x4(b, smem_u32(&Ksm[(nfp * 16 + b_row) * KW + st * 8 + b_col]));
                    mma_fp16(s[2 * nfp],     qa[st], b);
                    mma_fp16(s[2 * nfp + 1], qa[st], b + 2);
                }
            }

            // scale + causal mask
#pragma unroll
            for (int nf = 0; nf < 8; nf++) {
                int col0 = j * 64 + nf * 8 + 2 * lc;
                s[nf][0] = (col0     > rowA) ? -1e30f : s[nf][0] * scale;
                s[nf][1] = (col0 + 1 > rowA) ? -1e30f : s[nf][1] * scale;
                s[nf][2] = (col0     > rowB) ? -1e30f : s[nf][2] * scale;
                s[nf][3] = (col0 + 1 > rowB) ? -1e30f : s[nf][3] * scale;
            }

            // online softmax (once per 64 keys)
            float tA = -1e30f, tB = -1e30f;
#pragma unroll
            for (int nf = 0; nf < 8; nf++) {
                tA = fmaxf(tA, fmaxf(s[nf][0], s[nf][1]));
                tB = fmaxf(tB, fmaxf(s[nf][2], s[nf][3]));
            }
            tA = fmaxf(tA, __shfl_xor_sync(0xffffffffu, tA, 1));
            tA = fmaxf(tA, __shfl_xor_sync(0xffffffffu, tA, 2));
            tB = fmaxf(tB, __shfl_xor_sync(0xffffffffu, tB, 1));
            tB = fmaxf(tB, __shfl_xor_sync(0xffffffffu, tB, 2));

            float mAn = fmaxf(mA, tA), mBn = fmaxf(mB, tB);
            float aA = __expf(mA - mAn), aB = __expf(mB - mBn);
            float sA = 0.f, sB = 0.f;
#pragma unroll
            for (int nf = 0; nf < 8; nf++) {
                s[nf][0] = __expf(s[nf][0] - mAn);
                s[nf][1] = __expf(s[nf][1] - mAn);
                s[nf][2] = __expf(s[nf][2] - mBn);
                s[nf][3] = __expf(s[nf][3] - mBn);
                sA += s[nf][0] + s[nf][1];
                sB += s[nf][2] + s[nf][3];
            }
            sA += __shfl_xor_sync(0xffffffffu, sA, 1);
            sA += __shfl_xor_sync(0xffffffffu, sA, 2);
            sB += __shfl_xor_sync(0xffffffffu, sB, 1);
            sB += __shfl_xor_sync(0xffffffffu, sB, 2);
            lA = lA * aA + sA;
            lB = lB * aB + sB;
            mA = mAn; mB = mBn;
#pragma unroll
            for (int nf = 0; nf < 16; nf++) {
                o[nf][0] *= aA; o[nf][1] *= aA;
                o[nf][2] *= aB; o[nf][3] *= aB;
            }

            // O += P V  (4 k16 steps over 64 keys; FA2 P identity)
#pragma unroll
            for (int st = 0; st < 4; st++) {
                uint32_t pa[4];
                pa[0] = pack_h2(s[2 * st][0],     s[2 * st][1]);
                pa[1] = pack_h2(s[2 * st][2],     s[2 * st][3]);
                pa[2] = pack_h2(s[2 * st + 1][0], s[2 * st + 1][1]);
                pa[3] = pack_h2(s[2 * st + 1][2], s[2 * st + 1][3]);
#pragma unroll
                for (int nfp = 0; nfp < 8; nfp++) {
                    uint32_t b[4];
                    ldsm_x4_t(b, smem_u32(&Vsm[(st * 16 + a_row) * KW + nfp * 8 + a_col]));
                    mma_fp16(o[2 * nfp],     pa, b);
                    mma_fp16(o[2 * nfp + 1], pa, b + 2);
                }
            }
        }
    }

    float rA = 1.f / lA, rB = 1.f / lB;
#pragma unroll
    for (int nf = 0; nf < 16; nf++) {
        int col = h * HDIM + nf * 8 + 2 * lc;
        *(__half2*)(ctx + (size_t)rowA * HID + col) =
            __floats2half2_rn(o[nf][0] * rA, o[nf][1] * rA);
        *(__half2*)(ctx + (size_t)rowB * HID + col) =
            __floats2half2_rn(o[nf][2] * rB, o[nf][3] * rB);
    }
}

// ---------------------------------------------------------------------------
// launcher
// ---------------------------------------------------------------------------
extern "C" void kernel_launch(void* const* d_in, const int* in_sizes, int n_in,
                              void* d_out, int out_size)
{
    const float* hidden = nullptr;
    const float* w_qkv  = nullptr;
    const float* b_qkv  = nullptr;
    const float* w_proj = nullptr;
    for (int i = 0; i < n_in; i++) {
        long sz = in_sizes[i];
        const float* p = (const float*)d_in[i];
        if (sz == (long)HID * QKV_N)      w_qkv = p;
        else if (sz == (long)QKV_N)       b_qkv = p;
        else {
            if (!hidden) hidden = p; else w_proj = p;
        }
    }
    float* out = (float*)d_out;

    __half *qkv_h, *ctx_h, *hid_h, *w1t, *w2t;
    cudaGetSymbolAddress((void**)&qkv_h, g_qkv_h);
    cudaGetSymbolAddress((void**)&ctx_h, g_ctx_h);
    cudaGetSymbolAddress((void**)&hid_h, g_hid_h);
    cudaGetSymbolAddress((void**)&w1t,   g_w1t_h);
    cudaGetSymbolAddress((void**)&w2t,   g_w2t_h);

    cudaFuncSetAttribute(gemm_fp16_kernel<true, __half>,
                         cudaFuncAttributeMaxDynamicSharedMemorySize, GEMM_SMEM_BYTES);
    cudaFuncSetAttribute(gemm_fp16_kernel<false, float>,
                         cudaFuncAttributeMaxDynamicSharedMemorySize, GEMM_SMEM_BYTES);
    cudaFuncSetAttribute(flash_fp16_kernel,
                         cudaFuncAttributeMaxDynamicSharedMemorySize, FLASH_SMEM_BYTES);

    rope_table_kernel<<<(S_LEN * 64) / 256, 256>>>();
    convert_half_kernel<<<(S_LEN * HID / 4) / 256, 256>>>(hidden, hid_h, S_LEN * HID / 4);
    transpose_half_kernel<<<dim3(QKV_N / 32, HID / 32), dim3(32, 8)>>>(w_qkv, w1t, HID, QKV_N);
    transpose_half_kernel<<<dim3(HID / 32, HID / 32), dim3(32, 8)>>>(w_proj, w2t, HID, HID);

    gemm_fp16_kernel<true, __half>
        <<<dim3(QKV_N / 128, S_LEN / 128), 256, GEMM_SMEM_BYTES>>>(
        hid_h, w1t, b_qkv, qkv_h, S_LEN, QKV_N, HID);
    rope_apply_kernel<<<(S_LEN * NHEAD * 64) / 256, 256>>>(qkv_h);
    flash_fp16_kernel<<<dim3(S_LEN / 128, NHEAD), 256, FLASH_SMEM_BYTES>>>(qkv_h, ctx_h);
    gemm_fp16_kernel<false, float>
        <<<dim3(HID / 128, S_LEN / 128), 256, GEMM_SMEM_BYTES>>>(
        ctx_h, w2t, nullptr, out, S_LEN, HID, HID);
}